// round 9
// baseline (speedup 1.0000x reference)
#include <cuda_runtime.h>
#include <math.h>
#include <stdint.h>

#define B_   4
#define T_   1024
#define E_   1024
#define H_   16
#define DK_  64
#define M_   (B_ * T_)        // 4096 rows

// Scratch (allocation-free rule: __device__ globals)
__device__ float g_Q[M_ * E_];
__device__ float g_K[M_ * E_];
__device__ float g_V[M_ * E_];
__device__ float g_O[M_ * E_];
// tf32 pre-rounded copies
__device__ float g_q32[M_ * E_];
__device__ float g_k32[M_ * E_];
__device__ float g_v32[M_ * E_];
__device__ float g_W32[4 * E_ * E_];   // Wq, Wk, Wv, Wo

// ---------------------------------------------------------------------------
// helpers
// ---------------------------------------------------------------------------
__device__ __forceinline__ uint32_t smem_u32(const void* p) {
    uint32_t a;
    asm("{ .reg .u64 t; cvta.to.shared.u64 t, %1; cvt.u32.u64 %0, t; }"
        : "=r"(a) : "l"(p));
    return a;
}
__device__ __forceinline__ void cp_async16(uint32_t sdst, const void* gsrc) {
    asm volatile("cp.async.cg.shared.global [%0], [%1], 16;"
                 :: "r"(sdst), "l"(gsrc) : "memory");
}
#define CP_COMMIT() asm volatile("cp.async.commit_group;" ::: "memory")
#define CP_WAIT(n)  asm volatile("cp.async.wait_group %0;" :: "n"(n) : "memory")

__device__ __forceinline__ uint32_t f2tf32(float f) {
    uint32_t r;
    asm("cvt.rna.tf32.f32 %0, %1;" : "=r"(r) : "f"(f));
    return r;
}
__device__ __forceinline__ float ex2(float x) {
    float r; asm("ex2.approx.f32 %0, %1;" : "=f"(r) : "f"(x)); return r;
}
__device__ __forceinline__ void mma_tf32(float* c, const uint32_t* a, const uint32_t* b) {
    asm volatile(
        "mma.sync.aligned.m16n8k8.row.col.f32.tf32.tf32.f32 "
        "{%0,%1,%2,%3}, {%4,%5,%6,%7}, {%8,%9}, {%0,%1,%2,%3};"
        : "+f"(c[0]), "+f"(c[1]), "+f"(c[2]), "+f"(c[3])
        : "r"(a[0]), "r"(a[1]), "r"(a[2]), "r"(a[3]), "r"(b[0]), "r"(b[1]));
}

// ---------------------------------------------------------------------------
// Pre-round kernel: tf32-round q,k,v and the 4 weight matrices (one pass).
// ---------------------------------------------------------------------------
#define SEG_IN  (M_ * E_ / 4)      // 1,048,576 float4 per q/k/v
#define SEG_W   (E_ * E_ / 4)      //   262,144 float4 per weight
__global__ void __launch_bounds__(256)
preround(const float4* __restrict__ q, const float4* __restrict__ k,
         const float4* __restrict__ v,
         const float4* __restrict__ Wq, const float4* __restrict__ Wk,
         const float4* __restrict__ Wv, const float4* __restrict__ Wo,
         float4* __restrict__ rq, float4* __restrict__ rk,
         float4* __restrict__ rv, float4* __restrict__ rW)
{
    int i = blockIdx.x * 256 + threadIdx.x;       // 0 .. 4M-1
    if (i < 3 * SEG_IN) {
        const int seg = i / SEG_IN;
        const int off = i - seg * SEG_IN;
        const float4* s = (seg == 0) ? q : (seg == 1) ? k : v;
        float4* d       = (seg == 0) ? rq : (seg == 1) ? rk : rv;
        float4 x = s[off];
        x.x = __uint_as_float(f2tf32(x.x));
        x.y = __uint_as_float(f2tf32(x.y));
        x.z = __uint_as_float(f2tf32(x.z));
        x.w = __uint_as_float(f2tf32(x.w));
        d[off] = x;
    } else {
        i -= 3 * SEG_IN;
        const int seg  = i / SEG_W;
        const int loff = i - seg * SEG_W;
        float4 x = ((seg == 0) ? Wq : (seg == 1) ? Wk : (seg == 2) ? Wv : Wo)[loff];
        x.x = __uint_as_float(f2tf32(x.x));
        x.y = __uint_as_float(f2tf32(x.y));
        x.z = __uint_as_float(f2tf32(x.z));
        x.w = __uint_as_float(f2tf32(x.w));
        rW[i] = x;
    }
}

// ---------------------------------------------------------------------------
// tf32 mma.sync GEMM core:  C[4096,1024] = A[4096,1024] @ W[1024,1024]^T + bias
// 128x128 CTA tile, BK=32, 128 threads (4 warps 2x2), warp tile 64x64.
// THREE-stage cp.async pipeline: prefetch distance 2 k-tiles (> DRAM latency).
// One __syncthreads per iteration.
// ---------------------------------------------------------------------------
#define GBM 128
#define GBN 128
#define GBK 32
#define SSTRIDE 36
#define STAGE_FLOATS (GBM * SSTRIDE)                 // per A or B tile
#define STAGE_BYTES  (2 * STAGE_FLOATS * 4)          // A+B per stage: 36864
#define NSTAGE 3
#define GEMM_SMEM    (NSTAGE * STAGE_BYTES)          // 110592 bytes

__device__ __forceinline__ void gemm_load_tile(uint32_t sA, uint32_t sB,
                                               const float* __restrict__ A,
                                               const float* __restrict__ W,
                                               int m0, int n0, int kc, int tid)
{
    #pragma unroll
    for (int i = 0; i < 8; i++) {
        const int id = tid + i * 128;
        const int r  = id >> 3;
        const int c4 = (id & 7) * 4;
        cp_async16(sA + (r * SSTRIDE + c4) * 4, A + (size_t)(m0 + r) * E_ + kc + c4);
        cp_async16(sB + (r * SSTRIDE + c4) * 4, W + (size_t)(n0 + r) * E_ + kc + c4);
    }
}

template<int ROUND>
__device__ __forceinline__ void gemm_core(const float* __restrict__ A,
                                          const float* __restrict__ W,
                                          const float* __restrict__ bias,
                                          float* __restrict__ C)
{
    extern __shared__ __align__(16) float smem[];
    const uint32_t sbase = smem_u32(smem);

    const int tid  = threadIdx.x;
    const int wid  = tid >> 5;
    const int lane = tid & 31;
    const int g    = lane >> 2;
    const int t    = lane & 3;
    const int wm   = (wid >> 1) * 64;
    const int wn   = (wid & 1) * 64;
    const int m0   = blockIdx.y * GBM;
    const int n0   = blockIdx.x * GBN;

    float acc[4][8][4] = {};
    const int KTILES = E_ / GBK;   // 32

    // prologue: stages 0 and 1
    gemm_load_tile(sbase, sbase + STAGE_FLOATS * 4, A, W, m0, n0, 0, tid);
    CP_COMMIT();
    gemm_load_tile(sbase + STAGE_BYTES, sbase + STAGE_BYTES + STAGE_FLOATS * 4,
                   A, W, m0, n0, GBK, tid);
    CP_COMMIT();

    int s = 0;
    for (int kt = 0; kt < KTILES; kt++) {
        if (kt == KTILES - 1) { CP_WAIT(0); } else { CP_WAIT(1); }
        __syncthreads();   // tile kt resident; all warps done with compute kt-1

        if (kt + 2 < KTILES) {
            int ps = s + 2; if (ps >= NSTAGE) ps -= NSTAGE;
            const uint32_t pb = sbase + ps * STAGE_BYTES;
            gemm_load_tile(pb, pb + STAGE_FLOATS * 4, A, W, m0, n0, (kt + 2) * GBK, tid);
            CP_COMMIT();
        }

        const float* Asl = smem + s * (2 * STAGE_FLOATS);
        const float* Bsl = Asl + STAGE_FLOATS;

        #pragma unroll
        for (int kk = 0; kk < 4; kk++) {
            const int kb = kk * 8;
            uint32_t bf[8][2];
            #pragma unroll
            for (int ni = 0; ni < 8; ni++) {
                const int n = wn + ni * 8 + g;
                bf[ni][0] = __float_as_uint(Bsl[n * SSTRIDE + kb + t]);
                bf[ni][1] = __float_as_uint(Bsl[n * SSTRIDE + kb + t + 4]);
            }
            #pragma unroll
            for (int mi = 0; mi < 4; mi++) {
                const int r = wm + mi * 16;
                uint32_t af[4];
                af[0] = __float_as_uint(Asl[(r + g)     * SSTRIDE + kb + t]);
                af[1] = __float_as_uint(Asl[(r + g + 8) * SSTRIDE + kb + t]);
                af[2] = __float_as_uint(Asl[(r + g)     * SSTRIDE + kb + t + 4]);
                af[3] = __float_as_uint(Asl[(r + g + 8) * SSTRIDE + kb + t + 4]);
                #pragma unroll
                for (int ni = 0; ni < 8; ni++)
                    mma_tf32(acc[mi][ni], af, bf[ni]);
            }
        }

        s = s + 1; if (s >= NSTAGE) s = 0;
    }

    #pragma unroll
    for (int ni = 0; ni < 8; ni++) {
        const int col = n0 + wn + ni * 8 + 2 * t;
        const float2 bv = *(const float2*)(bias + col);
        #pragma unroll
        for (int mi = 0; mi < 4; mi++) {
            const int r0 = m0 + wm + mi * 16 + g;
            float2 o0, o1;
            o0.x = acc[mi][ni][0] + bv.x;
            o0.y = acc[mi][ni][1] + bv.y;
            o1.x = acc[mi][ni][2] + bv.x;
            o1.y = acc[mi][ni][3] + bv.y;
            if (ROUND) {
                o0.x = __uint_as_float(f2tf32(o0.x));
                o0.y = __uint_as_float(f2tf32(o0.y));
                o1.x = __uint_as_float(f2tf32(o1.x));
                o1.y = __uint_as_float(f2tf32(o1.y));
            }
            *(float2*)(C + (size_t)r0 * E_ + col)       = o0;
            *(float2*)(C + (size_t)(r0 + 8) * E_ + col) = o1;
        }
    }
}

// Merged Q/K/V projections: gridDim.z selects which; outputs tf32-rounded.
__global__ void __launch_bounds__(128)
gemm_qkv(const float* __restrict__ q,  const float* __restrict__ k,  const float* __restrict__ v,
         const float* __restrict__ Wqkv,
         const float* __restrict__ bq, const float* __restrict__ bk, const float* __restrict__ bv,
         float* __restrict__ Cq, float* __restrict__ Ck, float* __restrict__ Cv)
{
    const int z = blockIdx.z;
    if (z == 0)      gemm_core<1>(q, Wqkv,                 bq, Cq);
    else if (z == 1) gemm_core<1>(k, Wqkv + 1 * E_ * E_,   bk, Ck);
    else             gemm_core<1>(v, Wqkv + 2 * E_ * E_,   bv, Cv);
}

__global__ void __launch_bounds__(128)
gemm_o(const float* __restrict__ A, const float* __restrict__ W,
       const float* __restrict__ bias, float* __restrict__ C)
{
    gemm_core<0>(A, W, bias, C);
}

// ---------------------------------------------------------------------------
// Tensor-core flash attention (as R5); O stored tf32-rounded for gemm_o.
// ---------------------------------------------------------------------------
#define AST 68
#define KVSTG (64 * AST)
#define KS_OFF(s) ((s) * 2 * KVSTG)
#define VS_OFF(s) ((s) * 2 * KVSTG + KVSTG)
#define WS_OFF(s) (4 * KVSTG + (s) * 128)
#define QS_OFF    (4 * KVSTG + 256)
#define ATTN_SMEM ((QS_OFF + 128 * AST) * 4)

__global__ void __launch_bounds__(256, 1)
attn_tc(const float* __restrict__ Qp, const float* __restrict__ Kp,
        const float* __restrict__ Vp, const float* __restrict__ w,
        float* __restrict__ Op)
{
    extern __shared__ __align__(16) float sm[];
    const uint32_t sbase = smem_u32(sm);
    const int b   = blockIdx.z;
    const int h   = blockIdx.y;
    const int q0  = blockIdx.x * 128;
    const int tid = threadIdx.x;
    const int wid = tid >> 5;
    const int lane = tid & 31;
    const int g = lane >> 2;
    const int t = lane & 3;
    const int wq = wid * 16;

    {
        const float* Qg = Qp + (size_t)(b * T_ + q0) * E_ + h * DK_;
        #pragma unroll
        for (int i = 0; i < 8; i++) {
            const int id = tid + i * 256;
            const int r  = id >> 4;
            const int c4 = (id & 15) * 4;
            cp_async16(sbase + (QS_OFF + r * AST + c4) * 4, Qg + (size_t)r * E_ + c4);
        }
        CP_COMMIT();
    }
    {
        const float* Kg = Kp + (size_t)(b * T_) * E_ + h * DK_;
        const float* Vg = Vp + (size_t)(b * T_) * E_ + h * DK_;
        #pragma unroll
        for (int i = 0; i < 4; i++) {
            const int id = tid + i * 256;
            const int r  = id >> 4;
            const int c4 = (id & 15) * 4;
            cp_async16(sbase + (KS_OFF(0) + r * AST + c4) * 4, Kg + (size_t)r * E_ + c4);
            cp_async16(sbase + (VS_OFF(0) + r * AST + c4) * 4, Vg + (size_t)r * E_ + c4);
        }
        CP_COMMIT();
    }
    if (tid < 64) {
        const float wv = w[b * T_ + tid];
        sm[WS_OFF(0) + tid * 2 + 0] = wv * wv * 0.125f * 1.44269504f;
        sm[WS_OFF(0) + tid * 2 + 1] = (wv < 1e-5f) ? -INFINITY : 0.0f;
    }

    CP_WAIT(1);
    __syncthreads();

    uint32_t aq[8][4];
    #pragma unroll
    for (int ks = 0; ks < 8; ks++) {
        const int kb = ks * 8;
        aq[ks][0] = __float_as_uint(sm[QS_OFF + (wq + g)     * AST + kb + t]);
        aq[ks][1] = __float_as_uint(sm[QS_OFF + (wq + g + 8) * AST + kb + t]);
        aq[ks][2] = __float_as_uint(sm[QS_OFF + (wq + g)     * AST + kb + t + 4]);
        aq[ks][3] = __float_as_uint(sm[QS_OFF + (wq + g + 8) * AST + kb + t + 4]);
    }

    float acc[8][4] = {};
    float m0 = -INFINITY, m1 = -INFINITY, l0 = 0.f, l1 = 0.f;

    const int NT = T_ / 64;
    for (int kt = 0; kt < NT; kt++) {
        const int s = kt & 1;

        CP_WAIT(0);
        __syncthreads();

        if (kt + 1 < NT) {
            const int ns = 1 - s;
            const float* Kg = Kp + (size_t)(b * T_ + (kt + 1) * 64) * E_ + h * DK_;
            const float* Vg = Vp + (size_t)(b * T_ + (kt + 1) * 64) * E_ + h * DK_;
            #pragma unroll
            for (int i = 0; i < 4; i++) {
                const int id = tid + i * 256;
                const int r  = id >> 4;
                const int c4 = (id & 15) * 4;
                cp_async16(sbase + (KS_OFF(ns) + r * AST + c4) * 4, Kg + (size_t)r * E_ + c4);
                cp_async16(sbase + (VS_OFF(ns) + r * AST + c4) * 4, Vg + (size_t)r * E_ + c4);
            }
            CP_COMMIT();
            if (tid < 64) {
                const float wv = w[b * T_ + (kt + 1) * 64 + tid];
                sm[WS_OFF(ns) + tid * 2 + 0] = wv * wv * 0.125f * 1.44269504f;
                sm[WS_OFF(ns) + tid * 2 + 1] = (wv < 1e-5f) ? -INFINITY : 0.0f;
            }
        }

        const float* Ksl = sm + KS_OFF(s);
        const float* Vsl = sm + VS_OFF(s);
        const float* wsl = sm + WS_OFF(s);

        float sc[8][4] = {};
        #pragma unroll
        for (int ks = 0; ks < 8; ks++) {
            const int kb = ks * 8;
            #pragma unroll
            for (int nt = 0; nt < 8; nt++) {
                uint32_t bf[2];
                bf[0] = __float_as_uint(Ksl[(nt * 8 + g) * AST + kb + t]);
                bf[1] = __float_as_uint(Ksl[(nt * 8 + g) * AST + kb + t + 4]);
                mma_tf32(sc[nt], aq[ks], bf);
            }
        }

        float tmax0 = -INFINITY, tmax1 = -INFINITY;
        #pragma unroll
        for (int nt = 0; nt < 8; nt++) {
            const float4 wm4 = *(const float4*)&wsl[(nt * 8 + 2 * t) * 2];
            sc[nt][0] = sc[nt][0] * wm4.x + wm4.y;
            sc[nt][1] = sc[nt][1] * wm4.z + wm4.w;
            sc[nt][2] = sc[nt][2] * wm4.x + wm4.y;
            sc[nt][3] = sc[nt][3] * wm4.z + wm4.w;
            tmax0 = fmaxf(tmax0, fmaxf(sc[nt][0], sc[nt][1]));
            tmax1 = fmaxf(tmax1, fmaxf(sc[nt][2], sc[nt][3]));
        }
        tmax0 = fmaxf(tmax0, __shfl_xor_sync(0xffffffffu, tmax0, 1));
        tmax0 = fmaxf(tmax0, __shfl_xor_sync(0xffffffffu, tmax0, 2));
        tmax1 = fmaxf(tmax1, __shfl_xor_sync(0xffffffffu, tmax1, 1));
        tmax1 = fmaxf(tmax1, __shfl_xor_sync(0xffffffffu, tmax1, 2));

        const float nm0 = fmaxf(m0, tmax0);
        const float nm1 = fmaxf(m1, tmax1);
        const float sm0 = fmaxf(nm0, -1e38f);
        const float sm1 = fmaxf(nm1, -1e38f);
        const float c0  = ex2(fmaxf(m0, -1e38f) - sm0);
        const float c1  = ex2(fmaxf(m1, -1e38f) - sm1);
        m0 = nm0; m1 = nm1;
        l0 *= c0;  l1 *= c1;
        #pragma unroll
        for (int nt = 0; nt < 8; nt++) {
            acc[nt][0] *= c0; acc[nt][1] *= c0;
            acc[nt][2] *= c1; acc[nt][3] *= c1;
        }

        #pragma unroll
        for (int nt = 0; nt < 8; nt++) {
            sc[nt][0] = ex2(sc[nt][0] - sm0);
            sc[nt][1] = ex2(sc[nt][1] - sm0);
            sc[nt][2] = ex2(sc[nt][2] - sm1);
            sc[nt][3] = ex2(sc[nt][3] - sm1);
            l0 += sc[nt][0] + sc[nt][1];
            l1 += sc[nt][2] + sc[nt][3];
        }

        const int s0l = (lane & ~3) | (t >> 1);
        const int s1l = s0l + 2;
        const bool odd = (t & 1);
        #pragma unroll
        for (int ks = 0; ks < 8; ks++) {
            const float x0 = __shfl_sync(0xffffffffu, sc[ks][0], s0l);
            const float x1 = __shfl_sync(0xffffffffu, sc[ks][1], s0l);
            const float z0 = __shfl_sync(0xffffffffu, sc[ks][2], s0l);
            const float z1 = __shfl_sync(0xffffffffu, sc[ks][3], s0l);
            const float y0 = __shfl_sync(0xffffffffu, sc[ks][0], s1l);
            const float y1 = __shfl_sync(0xffffffffu, sc[ks][1], s1l);
            const float u0 = __shfl_sync(0xffffffffu, sc[ks][2], s1l);
            const float u1 = __shfl_sync(0xffffffffu, sc[ks][3], s1l);
            uint32_t ap[4];
            ap[0] = f2tf32(odd ? x1 : x0);
            ap[1] = f2tf32(odd ? z1 : z0);
            ap[2] = f2tf32(odd ? y1 : y0);
            ap[3] = f2tf32(odd ? u1 : u0);
            #pragma unroll
            for (int nd = 0; nd < 8; nd++) {
                uint32_t bf[2];
                bf[0] = __float_as_uint(Vsl[(ks * 8 + t)     * AST + nd * 8 + g]);
                bf[1] = __float_as_uint(Vsl[(ks * 8 + t + 4) * AST + nd * 8 + g]);
                mma_tf32(acc[nd], ap, bf);
            }
        }
    }

    l0 += __shfl_xor_sync(0xffffffffu, l0, 1);
    l0 += __shfl_xor_sync(0xffffffffu, l0, 2);
    l1 += __shfl_xor_sync(0xffffffffu, l1, 1);
    l1 += __shfl_xor_sync(0xffffffffu, l1, 2);
    const float inv0 = 1.f / l0;
    const float inv1 = 1.f / l1;

    const int row0 = b * T_ + q0 + wq + g;
    #pragma unroll
    for (int nd = 0; nd < 8; nd++) {
        const int col = h * DK_ + nd * 8 + 2 * t;
        float2 o0, o1;
        o0.x = __uint_as_float(f2tf32(acc[nd][0] * inv0));
        o0.y = __uint_as_float(f2tf32(acc[nd][1] * inv0));
        o1.x = __uint_as_float(f2tf32(acc[nd][2] * inv1));
        o1.y = __uint_as_float(f2tf32(acc[nd][3] * inv1));
        *(float2*)(Op + (size_t)row0 * E_ + col)       = o0;
        *(float2*)(Op + (size_t)(row0 + 8) * E_ + col) = o1;
    }
}

// ---------------------------------------------------------------------------
extern "C" void kernel_launch(void* const* d_in, const int* in_sizes, int n_in,
                              void* d_out, int out_size)
{
    const float* q  = (const float*)d_in[0];
    const float* k  = (const float*)d_in[1];
    const float* v  = (const float*)d_in[2];
    const float* w  = (const float*)d_in[3];
    const float* Wq = (const float*)d_in[4];
    const float* bq = (const float*)d_in[5];
    const float* Wk = (const float*)d_in[6];
    const float* bk = (const float*)d_in[7];
    const float* Wv = (const float*)d_in[8];
    const float* bv = (const float*)d_in[9];
    const float* Wo = (const float*)d_in[10];
    const float* bo = (const float*)d_in[11];
    float* out = (float*)d_out;

    float *Qp, *Kp, *Vp, *Op, *rq, *rk, *rv, *rW;
    cudaGetSymbolAddress((void**)&Qp, g_Q);
    cudaGetSymbolAddress((void**)&Kp, g_K);
    cudaGetSymbolAddress((void**)&Vp, g_V);
    cudaGetSymbolAddress((void**)&Op, g_O);
    cudaGetSymbolAddress((void**)&rq, g_q32);
    cudaGetSymbolAddress((void**)&rk, g_k32);
    cudaGetSymbolAddress((void**)&rv, g_v32);
    cudaGetSymbolAddress((void**)&rW, g_W32);

    cudaFuncSetAttribute(gemm_qkv, cudaFuncAttributeMaxDynamicSharedMemorySize, GEMM_SMEM);
    cudaFuncSetAttribute(gemm_o,   cudaFuncAttributeMaxDynamicSharedMemorySize, GEMM_SMEM);
    cudaFuncSetAttribute(attn_tc,  cudaFuncAttributeMaxDynamicSharedMemorySize, ATTN_SMEM);

    // 1) pre-round q,k,v + all weights to tf32 (order in g_W32: Wq, Wk, Wv, Wo)
    preround<<<16384, 256>>>((const float4*)q, (const float4*)k, (const float4*)v,
                             (const float4*)Wq, (const float4*)Wk,
                             (const float4*)Wv, (const float4*)Wo,
                             (float4*)rq, (float4*)rk, (float4*)rv, (float4*)rW);

    // 2) QKV projections
    const dim3 qkvGrid(E_ / GBN, M_ / GBM, 3);   // (8, 32, 3)
    gemm_qkv<<<qkvGrid, 128, GEMM_SMEM>>>(rq, rk, rv, rW, bq, bk, bv, Qp, Kp, Vp);

    // 3) attention
    const dim3 aGrid(T_ / 128, H_, B_);          // (8, 16, 4)
    attn_tc<<<aGrid, 256, ATTN_SMEM>>>(Qp, Kp, Vp, w, Op);

    // 4) output projection
    const dim3 oGrid(E_ / GBN, M_ / GBM);        // (8, 32)
    gemm_o<<<oGrid, 128, GEMM_SMEM>>>(Op, rW + 3 * (size_t)E_ * E_, bo, out);
}

// round 13
// speedup vs baseline: 1.8724x; 1.8724x over previous
#include <cuda_runtime.h>
#include <cuda_fp16.h>
#include <math.h>
#include <stdint.h>

#define B_   4
#define T_   1024
#define E_   1024
#define H_   16
#define DK_  64
#define M_   (B_ * T_)        // 4096 rows

// Scratch (allocation-free rule: __device__ globals) — all fp16
__device__ __half g_qh[M_ * E_];
__device__ __half g_kh[M_ * E_];
__device__ __half g_vh[M_ * E_];
__device__ __half g_Wh[4 * E_ * E_];   // Wq, Wk, Wv, Wo
__device__ __half g_Qh[M_ * E_];
__device__ __half g_Kh[M_ * E_];
__device__ __half g_Vth[M_ * E_];      // V^T per head: [b][h][dk][seq]
__device__ __half g_Oh[M_ * E_];

// ---------------------------------------------------------------------------
// helpers
// ---------------------------------------------------------------------------
__device__ __forceinline__ uint32_t smem_u32(const void* p) {
    uint32_t a;
    asm("{ .reg .u64 t; cvta.to.shared.u64 t, %1; cvt.u32.u64 %0, t; }"
        : "=r"(a) : "l"(p));
    return a;
}
__device__ __forceinline__ void cp_async16(uint32_t sdst, const void* gsrc) {
    asm volatile("cp.async.cg.shared.global [%0], [%1], 16;"
                 :: "r"(sdst), "l"(gsrc) : "memory");
}
#define CP_COMMIT() asm volatile("cp.async.commit_group;" ::: "memory")
#define CP_WAIT(n)  asm volatile("cp.async.wait_group %0;" :: "n"(n) : "memory")

__device__ __forceinline__ float ex2(float x) {
    float r; asm("ex2.approx.f32 %0, %1;" : "=f"(r) : "f"(x)); return r;
}
__device__ __forceinline__ uint32_t pack_h2(float lo, float hi) {
    __half2 h = __floats2half2_rn(lo, hi);
    return *(uint32_t*)&h;
}
__device__ __forceinline__ void mma_f16(float* c, const uint32_t* a, const uint32_t* b) {
    asm volatile(
        "mma.sync.aligned.m16n8k16.row.col.f32.f16.f16.f32 "
        "{%0,%1,%2,%3}, {%4,%5,%6,%7}, {%8,%9}, {%0,%1,%2,%3};"
        : "+f"(c[0]), "+f"(c[1]), "+f"(c[2]), "+f"(c[3])
        : "r"(a[0]), "r"(a[1]), "r"(a[2]), "r"(a[3]), "r"(b[0]), "r"(b[1]));
}

// ---------------------------------------------------------------------------
// Pre-convert kernel: fp32 -> fp16 for q,k,v and the 4 weight matrices.
// 4M float4 items; grid 16384 x 256 covers exactly.
// ---------------------------------------------------------------------------
#define SEG_IN  (M_ * E_ / 4)      // 1,048,576 float4 per q/k/v
#define SEG_W   (E_ * E_ / 4)
__global__ void __launch_bounds__(256)
preconv(const float4* __restrict__ q, const float4* __restrict__ k,
        const float4* __restrict__ v,
        const float4* __restrict__ Wq, const float4* __restrict__ Wk,
        const float4* __restrict__ Wv, const float4* __restrict__ Wo,
        __half* __restrict__ qh, __half* __restrict__ kh,
        __half* __restrict__ vh, __half* __restrict__ Wh)
{
    int i = blockIdx.x * 256 + threadIdx.x;       // 0 .. 4M-1
    float4 x;
    __half* dst;
    int off;
    if (i < 3 * SEG_IN) {
        const int seg = i / SEG_IN;
        off = i - seg * SEG_IN;
        x   = ((seg == 0) ? q : (seg == 1) ? k : v)[off];
        dst = (seg == 0) ? qh : (seg == 1) ? kh : vh;
    } else {
        i -= 3 * SEG_IN;
        const int seg = i / SEG_W;
        x   = ((seg == 0) ? Wq : (seg == 1) ? Wk : (seg == 2) ? Wv : Wo)[i - seg * SEG_W];
        dst = Wh;
        off = i;
    }
    uint2 u;
    u.x = pack_h2(x.x, x.y);
    u.y = pack_h2(x.z, x.w);
    *(uint2*)(dst + 4 * off) = u;
}

// ---------------------------------------------------------------------------
// fp16 mma.sync GEMM core:  C[4096,1024] = A[4096,1024] @ W[1024,1024]^T + bias
// 128x128 CTA tile, BK=64 halves, 128 threads (4 warps 2x2), warp tile 64x64.
// 3-stage cp.async pipeline. m16n8k16, fp32 accumulate.
// OUT: 0 = fp32 store + bias; 1 = fp16 store + bias; 2 = fp16 V^T scatter.
// ---------------------------------------------------------------------------
#define GBM 128
#define GBN 128
#define GBK 64
#define STRH 72                                   // halves per smem row
#define TILE_HALVES (128 * STRH)                  // 9216
#define STAGE_BYTES (2 * TILE_HALVES * 2)         // 36864 (A+B)
#define NSTAGE 3
#define GEMM_SMEM (NSTAGE * STAGE_BYTES)          // 110592

__device__ __forceinline__ void gload(uint32_t sA, uint32_t sB,
                                      const __half* __restrict__ A,
                                      const __half* __restrict__ W,
                                      int m0, int n0, int kc, int tid)
{
    #pragma unroll
    for (int i = 0; i < 8; i++) {
        const int id = tid + i * 128;             // 0..1023
        const int r  = id >> 3;                   // 0..127
        const int c8 = (id & 7) * 8;              // halves
        cp_async16(sA + (r * STRH + c8) * 2, A + (size_t)(m0 + r) * E_ + kc + c8);
        cp_async16(sB + (r * STRH + c8) * 2, W + (size_t)(n0 + r) * E_ + kc + c8);
    }
}

template<int OUT>
__device__ __forceinline__ void gemm_core(const __half* __restrict__ A,
                                          const __half* __restrict__ W,
                                          const float* __restrict__ bias,
                                          void* __restrict__ Cout)
{
    extern __shared__ __align__(16) char smc[];
    const uint32_t sbase = smem_u32(smc);

    const int tid  = threadIdx.x;
    const int wid  = tid >> 5;
    const int lane = tid & 31;
    const int g    = lane >> 2;
    const int t    = lane & 3;
    const int wm   = (wid >> 1) * 64;
    const int wn   = (wid & 1) * 64;
    const int m0   = blockIdx.y * GBM;
    const int n0   = blockIdx.x * GBN;

    float acc[4][8][4] = {};
    const int KTILES = E_ / GBK;   // 16

    gload(sbase, sbase + TILE_HALVES * 2, A, W, m0, n0, 0, tid);
    CP_COMMIT();
    gload(sbase + STAGE_BYTES, sbase + STAGE_BYTES + TILE_HALVES * 2,
          A, W, m0, n0, GBK, tid);
    CP_COMMIT();

    int s = 0;
    for (int kt = 0; kt < KTILES; kt++) {
        if (kt == KTILES - 1) { CP_WAIT(0); } else { CP_WAIT(1); }
        __syncthreads();

        if (kt + 2 < KTILES) {
            int ps = s + 2; if (ps >= NSTAGE) ps -= NSTAGE;
            const uint32_t pb = sbase + ps * STAGE_BYTES;
            gload(pb, pb + TILE_HALVES * 2, A, W, m0, n0, (kt + 2) * GBK, tid);
            CP_COMMIT();
        }

        const uint32_t* Aw = (const uint32_t*)(smc + s * STAGE_BYTES);
        const uint32_t* Bw = Aw + TILE_HALVES / 2;

        #pragma unroll
        for (int kk = 0; kk < 4; kk++) {           // 4 k-blocks of 16
            const int kw = kk * 8 + t;             // word offset in row
            uint32_t bf[8][2];
            #pragma unroll
            for (int ni = 0; ni < 8; ni++) {
                const int n = wn + ni * 8 + g;
                bf[ni][0] = Bw[n * 36 + kw];
                bf[ni][1] = Bw[n * 36 + kw + 4];
            }
            #pragma unroll
            for (int mi = 0; mi < 4; mi++) {
                const int r = wm + mi * 16 + g;
                uint32_t af[4];
                af[0] = Aw[r * 36 + kw];
                af[1] = Aw[(r + 8) * 36 + kw];
                af[2] = Aw[r * 36 + kw + 4];
                af[3] = Aw[(r + 8) * 36 + kw + 4];
                #pragma unroll
                for (int ni = 0; ni < 8; ni++)
                    mma_f16(acc[mi][ni], af, bf[ni]);
            }
        }

        s = s + 1; if (s >= NSTAGE) s = 0;
    }

    #pragma unroll
    for (int ni = 0; ni < 8; ni++) {
        const int col = n0 + wn + ni * 8 + 2 * t;
        const float2 bv = *(const float2*)(bias + col);
        #pragma unroll
        for (int mi = 0; mi < 4; mi++) {
            const int r0 = m0 + wm + mi * 16 + g;
            const float e0 = acc[mi][ni][0] + bv.x;
            const float e1 = acc[mi][ni][1] + bv.y;
            const float e2 = acc[mi][ni][2] + bv.x;
            const float e3 = acc[mi][ni][3] + bv.y;
            if (OUT == 0) {
                float* Cf = (float*)Cout;
                *(float2*)(Cf + (size_t)r0 * E_ + col)       = make_float2(e0, e1);
                *(float2*)(Cf + (size_t)(r0 + 8) * E_ + col) = make_float2(e2, e3);
            } else if (OUT == 1) {
                __half* Ch = (__half*)Cout;
                *(__half2*)(Ch + (size_t)r0 * E_ + col)       = __floats2half2_rn(e0, e1);
                *(__half2*)(Ch + (size_t)(r0 + 8) * E_ + col) = __floats2half2_rn(e2, e3);
            } else {
                // V^T scatter: Vt[((b*H + h)*DK + dk)*T + seq]
                __half* Vt = (__half*)Cout;
                const int bb  = r0 >> 10;
                const int seq = r0 & 1023;
                const size_t base = ((size_t)(bb * H_ + (col >> 6)) * DK_ + (col & 63)) * T_ + seq;
                Vt[base]          = __float2half_rn(e0);
                Vt[base + T_]     = __float2half_rn(e1);
                Vt[base + 8]      = __float2half_rn(e2);
                Vt[base + T_ + 8] = __float2half_rn(e3);
            }
        }
    }
}

__global__ void __launch_bounds__(128)
gemm_qkv(const __half* __restrict__ q, const __half* __restrict__ k, const __half* __restrict__ v,
         const __half* __restrict__ Wh,
         const float* __restrict__ bq, const float* __restrict__ bk, const float* __restrict__ bv,
         __half* __restrict__ Cq, __half* __restrict__ Ck, __half* __restrict__ CvT)
{
    const int z = blockIdx.z;
    if (z == 0)      gemm_core<1>(q, Wh,                 bq, Cq);
    else if (z == 1) gemm_core<1>(k, Wh + 1 * E_ * E_,   bk, Ck);
    else             gemm_core<2>(v, Wh + 2 * E_ * E_,   bv, CvT);
}

__global__ void __launch_bounds__(128)
gemm_o(const __half* __restrict__ A, const __half* __restrict__ W,
       const float* __restrict__ bias, float* __restrict__ C)
{
    gemm_core<0>(A, W, bias, C);
}

// ---------------------------------------------------------------------------
// fp16 tensor-core flash attention.
// grid (T/128, H, B), 256 threads = 8 warps x 16 query rows.
// K tiles [64 keys][64 dk], V^T tiles [64 dk][64 keys], double-buffered.
// m16n8k16; P repacks to fp16 A-frags with NO shuffles (C-layout pairs align).
// ---------------------------------------------------------------------------
#define ASTH 72
#define KHALF (64 * ASTH)                          // 4608 halves/stage tile
#define KOFF(s) ((s) * KHALF)
#define VOFF(s) (2 * KHALF + (s) * KHALF)
#define QOFF    (4 * KHALF)                        // 18432
#define WSB     ((QOFF + 128 * ASTH) * 2)          // ws float region byte offset: 55296
#define ATTN_SMEM (WSB + 2 * 128 * 4)              // 56320

__global__ void __launch_bounds__(256)
attn_tc(const __half* __restrict__ Qh, const __half* __restrict__ Kh,
        const __half* __restrict__ Vt, const float* __restrict__ w,
        __half* __restrict__ Oh)
{
    extern __shared__ __align__(16) char smc[];
    __half* smh = (__half*)smc;
    float* wsf  = (float*)(smc + WSB);
    const uint32_t sbase = smem_u32(smc);
    const int b   = blockIdx.z;
    const int h   = blockIdx.y;
    const int q0  = blockIdx.x * 128;
    const int tid = threadIdx.x;
    const int wid = tid >> 5;
    const int lane = tid & 31;
    const int g = lane >> 2;
    const int t = lane & 3;
    const int wq = wid * 16;

    // stage Q (group 0)
    {
        const __half* Qg = Qh + (size_t)(b * T_ + q0) * E_ + h * DK_;
        #pragma unroll
        for (int i = 0; i < 4; i++) {
            const int id = tid + i * 256;          // 0..1023
            const int r  = id >> 3;
            const int c8 = (id & 7) * 8;
            cp_async16(sbase + (QOFF + r * ASTH + c8) * 2, Qg + (size_t)r * E_ + c8);
        }
        CP_COMMIT();
    }
    // stage K/V tile 0 (group 1)
    {
        const __half* Kg = Kh + (size_t)(b * T_) * E_ + h * DK_;
        const __half* Vg = Vt + (size_t)((b * H_ + h) * DK_) * T_;
        #pragma unroll
        for (int i = 0; i < 2; i++) {
            const int id = tid + i * 256;          // 0..511
            const int r  = id >> 3;                // 0..63
            const int c8 = (id & 7) * 8;
            cp_async16(sbase + (KOFF(0) + r * ASTH + c8) * 2, Kg + (size_t)r * E_ + c8);
            cp_async16(sbase + (VOFF(0) + r * ASTH + c8) * 2, Vg + (size_t)r * T_ + c8);
        }
        CP_COMMIT();
    }
    if (tid < 64) {
        const float wv = w[b * T_ + tid];
        wsf[tid * 2 + 0] = wv * wv * 0.125f * 1.44269504f;
        wsf[tid * 2 + 1] = (wv < 1e-5f) ? -INFINITY : 0.0f;
    }

    CP_WAIT(1);
    __syncthreads();

    // Q fragments: aq[ks][4] for 4 k-blocks of 16 dk
    const uint32_t* Qw = (const uint32_t*)(smh + QOFF);
    uint32_t aq[4][4];
    #pragma unroll
    for (int ks = 0; ks < 4; ks++) {
        const int kw = ks * 8 + t;
        aq[ks][0] = Qw[(wq + g) * 36 + kw];
        aq[ks][1] = Qw[(wq + g + 8) * 36 + kw];
        aq[ks][2] = Qw[(wq + g) * 36 + kw + 4];
        aq[ks][3] = Qw[(wq + g + 8) * 36 + kw + 4];
    }

    float acc[8][4] = {};
    float m0 = -INFINITY, m1 = -INFINITY, l0 = 0.f, l1 = 0.f;

    const int NT = T_ / 64;   // 16
    for (int kt = 0; kt < NT; kt++) {
        const int s = kt & 1;

        CP_WAIT(0);
        __syncthreads();

        if (kt + 1 < NT) {
            const int ns = 1 - s;
            const __half* Kg = Kh + (size_t)(b * T_ + (kt + 1) * 64) * E_ + h * DK_;
            const __half* Vg = Vt + (size_t)((b * H_ + h) * DK_) * T_ + (kt + 1) * 64;
            #pragma unroll
            for (int i = 0; i < 2; i++) {
                const int id = tid + i * 256;
                const int r  = id >> 3;
                const int c8 = (id & 7) * 8;
                cp_async16(sbase + (KOFF(ns) + r * ASTH + c8) * 2, Kg + (size_t)r * E_ + c8);
                cp_async16(sbase + (VOFF(ns) + r * ASTH + c8) * 2, Vg + (size_t)r * T_ + c8);
            }
            CP_COMMIT();
            if (tid < 64) {
                const float wv = w[b * T_ + (kt + 1) * 64 + tid];
                wsf[ns * 128 + tid * 2 + 0] = wv * wv * 0.125f * 1.44269504f;
                wsf[ns * 128 + tid * 2 + 1] = (wv < 1e-5f) ? -INFINITY : 0.0f;
            }
        }

        const uint32_t* Kw = (const uint32_t*)(smh + KOFF(s));
        const uint32_t* Vw = (const uint32_t*)(smh + VOFF(s));
        const float* wsl = wsf + s * 128;

        // ---- S = Q K^T (16x64 per warp), 32 MMAs ----
        float sc[8][4] = {};
        #pragma unroll
        for (int ks = 0; ks < 4; ks++) {
            const int kw = ks * 8 + t;
            #pragma unroll
            for (int nt = 0; nt < 8; nt++) {
                uint32_t bf[2];
                bf[0] = Kw[(nt * 8 + g) * 36 + kw];
                bf[1] = Kw[(nt * 8 + g) * 36 + kw + 4];
                mma_f16(sc[nt], aq[ks], bf);
            }
        }

        // ---- scale + mask + row max ----
        float tmax0 = -INFINITY, tmax1 = -INFINITY;
        #pragma unroll
        for (int nt = 0; nt < 8; nt++) {
            const float4 wm4 = *(const float4*)&wsl[(nt * 8 + 2 * t) * 2];
            sc[nt][0] = sc[nt][0] * wm4.x + wm4.y;
            sc[nt][1] = sc[nt][1] * wm4.z + wm4.w;
            sc[nt][2] = sc[nt][2] * wm4.x + wm4.y;
            sc[nt][3] = sc[nt][3] * wm4.z + wm4.w;
            tmax0 = fmaxf(tmax0, fmaxf(sc[nt][0], sc[nt][1]));
            tmax1 = fmaxf(tmax1, fmaxf(sc[nt][2], sc[nt][3]));
        }
        tmax0 = fmaxf(tmax0, __shfl_xor_sync(0xffffffffu, tmax0, 1));
        tmax0 = fmaxf(tmax0, __shfl_xor_sync(0xffffffffu, tmax0, 2));
        tmax1 = fmaxf(tmax1, __shfl_xor_sync(0xffffffffu, tmax1, 1));
        tmax1 = fmaxf(tmax1, __shfl_xor_sync(0xffffffffu, tmax1, 2));

        const float nm0 = fmaxf(m0, tmax0);
        const float nm1 = fmaxf(m1, tmax1);
        const float sm0 = fmaxf(nm0, -1e38f);
        const float sm1 = fmaxf(nm1, -1e38f);
        const float c0  = ex2(fmaxf(m0, -1e38f) - sm0);
        const float c1  = ex2(fmaxf(m1, -1e38f) - sm1);
        m0 = nm0; m1 = nm1;
        l0 *= c0;  l1 *= c1;
        #pragma unroll
        for (int nt = 0; nt < 8; nt++) {
            acc[nt][0] *= c0; acc[nt][1] *= c0;
            acc[nt][2] *= c1; acc[nt][3] *= c1;
        }

        // ---- p = exp2(s - m) ----
        #pragma unroll
        for (int nt = 0; nt < 8; nt++) {
            sc[nt][0] = ex2(sc[nt][0] - sm0);
            sc[nt][1] = ex2(sc[nt][1] - sm0);
            sc[nt][2] = ex2(sc[nt][2] - sm1);
            sc[nt][3] = ex2(sc[nt][3] - sm1);
            l0 += sc[nt][0] + sc[nt][1];
            l1 += sc[nt][2] + sc[nt][3];
        }

        // ---- O += P V : fp16 A-frags align with C-layout (no shuffles) ----
        #pragma unroll
        for (int ks = 0; ks < 4; ks++) {          // key blocks of 16
            uint32_t ap[4];
            ap[0] = pack_h2(sc[2 * ks][0],     sc[2 * ks][1]);
            ap[1] = pack_h2(sc[2 * ks][2],     sc[2 * ks][3]);
            ap[2] = pack_h2(sc[2 * ks + 1][0], sc[2 * ks + 1][1]);
            ap[3] = pack_h2(sc[2 * ks + 1][2], sc[2 * ks + 1][3]);
            const int kw = ks * 8 + t;
            #pragma unroll
            for (int nd = 0; nd < 8; nd++) {
                uint32_t bf[2];
                bf[0] = Vw[(nd * 8 + g) * 36 + kw];
                bf[1] = Vw[(nd * 8 + g) * 36 + kw + 4];
                mma_f16(acc[nd], ap, bf);
            }
        }
    }

    // ---- finalize ----
    l0 += __shfl_xor_sync(0xffffffffu, l0, 1);
    l0 += __shfl_xor_sync(0xffffffffu, l0, 2);
    l1 += __shfl_xor_sync(0xffffffffu, l1, 1);
    l1 += __shfl_xor_sync(0xffffffffu, l1, 2);
    const float inv0 = 1.f / l0;
    const float inv1 = 1.f / l1;

    const int row0 = b * T_ + q0 + wq + g;
    #pragma unroll
    for (int nd = 0; nd < 8; nd++) {
        const int col = h * DK_ + nd * 8 + 2 * t;
        *(__half2*)(Oh + (size_t)row0 * E_ + col) =
            __floats2half2_rn(acc[nd][0] * inv0, acc[nd][1] * inv0);
        *(__half2*)(Oh + (size_t)(row0 + 8) * E_ + col) =
            __floats2half2_rn(acc[nd][2] * inv1, acc[nd][3] * inv1);
    }
}

// ---------------------------------------------------------------------------
extern "C" void kernel_launch(void* const* d_in, const int* in_sizes, int n_in,
                              void* d_out, int out_size)
{
    const float* q  = (const float*)d_in[0];
    const float* k  = (const float*)d_in[1];
    const float* v  = (const float*)d_in[2];
    const float* w  = (const float*)d_in[3];
    const float* Wq = (const float*)d_in[4];
    const float* bq = (const float*)d_in[5];
    const float* Wk = (const float*)d_in[6];
    const float* bk = (const float*)d_in[7];
    const float* Wv = (const float*)d_in[8];
    const float* bv = (const float*)d_in[9];
    const float* Wo = (const float*)d_in[10];
    const float* bo = (const float*)d_in[11];
    float* out = (float*)d_out;

    __half *qh, *kh, *vh, *Wh, *Qh, *Kh, *Vth, *Ohp;
    cudaGetSymbolAddress((void**)&qh,  g_qh);
    cudaGetSymbolAddress((void**)&kh,  g_kh);
    cudaGetSymbolAddress((void**)&vh,  g_vh);
    cudaGetSymbolAddress((void**)&Wh,  g_Wh);
    cudaGetSymbolAddress((void**)&Qh,  g_Qh);
    cudaGetSymbolAddress((void**)&Kh,  g_Kh);
    cudaGetSymbolAddress((void**)&Vth, g_Vth);
    cudaGetSymbolAddress((void**)&Ohp, g_Oh);

    cudaFuncSetAttribute(gemm_qkv, cudaFuncAttributeMaxDynamicSharedMemorySize, GEMM_SMEM);
    cudaFuncSetAttribute(gemm_o,   cudaFuncAttributeMaxDynamicSharedMemorySize, GEMM_SMEM);
    cudaFuncSetAttribute(attn_tc,  cudaFuncAttributeMaxDynamicSharedMemorySize, ATTN_SMEM);

    // 1) convert inputs + weights to fp16
    preconv<<<16384, 256>>>((const float4*)q, (const float4*)k, (const float4*)v,
                            (const float4*)Wq, (const float4*)Wk,
                            (const float4*)Wv, (const float4*)Wo,
                            qh, kh, vh, Wh);

    // 2) QKV projections (V written transposed per head)
    const dim3 qkvGrid(E_ / GBN, M_ / GBM, 3);   // (8, 32, 3)
    gemm_qkv<<<qkvGrid, 128, GEMM_SMEM>>>(qh, kh, vh, Wh, bq, bk, bv, Qh, Kh, Vth);

    // 3) attention
    const dim3 aGrid(T_ / 128, H_, B_);          // (8, 16, 4)
    attn_tc<<<aGrid, 256, ATTN_SMEM>>>(Qh, Kh, Vth, w, Ohp);

    // 4) output projection
    const dim3 oGrid(E_ / GBN, M_ / GBM);        // (8, 32)
    gemm_o<<<oGrid, 128, GEMM_SMEM>>>(Ohp, Wh + 3 * (size_t)E_ * E_, bo, out);
}

// round 14
// speedup vs baseline: 1.8895x; 1.0091x over previous
#include <cuda_runtime.h>
#include <cuda_fp16.h>
#include <math.h>
#include <stdint.h>

#define B_   4
#define T_   1024
#define E_   1024
#define H_   16
#define DK_  64
#define M_   (B_ * T_)        // 4096 rows

// Scratch (allocation-free rule: __device__ globals) — all fp16
__device__ __half g_qh[M_ * E_];
__device__ __half g_kh[M_ * E_];
__device__ __half g_vh[M_ * E_];
__device__ __half g_Wh[4 * E_ * E_];   // Wq, Wk, Wv, Wo
__device__ __half g_Qh[M_ * E_];
__device__ __half g_Kh[M_ * E_];
__device__ __half g_Vth[M_ * E_];      // V^T per head: [b][h][dk][seq]
__device__ __half g_Oh[M_ * E_];

// ---------------------------------------------------------------------------
// helpers
// ---------------------------------------------------------------------------
__device__ __forceinline__ uint32_t smem_u32(const void* p) {
    uint32_t a;
    asm("{ .reg .u64 t; cvta.to.shared.u64 t, %1; cvt.u32.u64 %0, t; }"
        : "=r"(a) : "l"(p));
    return a;
}
__device__ __forceinline__ void cp_async16(uint32_t sdst, const void* gsrc) {
    asm volatile("cp.async.cg.shared.global [%0], [%1], 16;"
                 :: "r"(sdst), "l"(gsrc) : "memory");
}
#define CP_COMMIT() asm volatile("cp.async.commit_group;" ::: "memory")
#define CP_WAIT(n)  asm volatile("cp.async.wait_group %0;" :: "n"(n) : "memory")

__device__ __forceinline__ float ex2(float x) {
    float r; asm("ex2.approx.f32 %0, %1;" : "=f"(r) : "f"(x)); return r;
}
__device__ __forceinline__ uint32_t pack_h2(float lo, float hi) {
    __half2 h = __floats2half2_rn(lo, hi);
    return *(uint32_t*)&h;
}
__device__ __forceinline__ void mma_f16(float* c, const uint32_t* a, const uint32_t* b) {
    asm volatile(
        "mma.sync.aligned.m16n8k16.row.col.f32.f16.f16.f32 "
        "{%0,%1,%2,%3}, {%4,%5,%6,%7}, {%8,%9}, {%0,%1,%2,%3};"
        : "+f"(c[0]), "+f"(c[1]), "+f"(c[2]), "+f"(c[3])
        : "r"(a[0]), "r"(a[1]), "r"(a[2]), "r"(a[3]), "r"(b[0]), "r"(b[1]));
}
__device__ __forceinline__ void ldsm4(uint32_t* r, uint32_t addr) {
    asm volatile("ldmatrix.sync.aligned.m8n8.x4.shared.b16 {%0,%1,%2,%3}, [%4];"
        : "=r"(r[0]), "=r"(r[1]), "=r"(r[2]), "=r"(r[3]) : "r"(addr));
}

// ---------------------------------------------------------------------------
// Pre-convert kernel: fp32 -> fp16 for q,k,v and the 4 weight matrices.
// ---------------------------------------------------------------------------
#define SEG_IN  (M_ * E_ / 4)      // 1,048,576 float4 per q/k/v
#define SEG_W   (E_ * E_ / 4)
__global__ void __launch_bounds__(256)
preconv(const float4* __restrict__ q, const float4* __restrict__ k,
        const float4* __restrict__ v,
        const float4* __restrict__ Wq, const float4* __restrict__ Wk,
        const float4* __restrict__ Wv, const float4* __restrict__ Wo,
        __half* __restrict__ qh, __half* __restrict__ kh,
        __half* __restrict__ vh, __half* __restrict__ Wh)
{
    int i = blockIdx.x * 256 + threadIdx.x;       // 0 .. 4M-1
    float4 x;
    __half* dst;
    int off;
    if (i < 3 * SEG_IN) {
        const int seg = i / SEG_IN;
        off = i - seg * SEG_IN;
        x   = ((seg == 0) ? q : (seg == 1) ? k : v)[off];
        dst = (seg == 0) ? qh : (seg == 1) ? kh : vh;
    } else {
        i -= 3 * SEG_IN;
        const int seg = i / SEG_W;
        x   = ((seg == 0) ? Wq : (seg == 1) ? Wk : (seg == 2) ? Wv : Wo)[i - seg * SEG_W];
        dst = Wh;
        off = i;
    }
    uint2 u;
    u.x = pack_h2(x.x, x.y);
    u.y = pack_h2(x.z, x.w);
    *(uint2*)(dst + 4 * off) = u;
}

// ---------------------------------------------------------------------------
// fp16 mma.sync GEMM core:  C[4096,1024] = A[4096,1024] @ W[1024,1024]^T + bias
// 128x128 CTA tile, BK=64 halves, 128 threads (4 warps 2x2), warp tile 64x64.
// 3-stage cp.async pipeline; ldmatrix.x4 fragment loads (8 per kk vs 32 LDS);
// B fragments double-buffered across kk steps.
// OUT: 0 = fp32 store + bias; 1 = fp16 store + bias; 2 = fp16 V^T scatter.
// ---------------------------------------------------------------------------
#define GBM 128
#define GBN 128
#define GBK 64
#define STRH 72                                   // halves per smem row
#define TILE_HALVES (128 * STRH)                  // 9216
#define STAGE_BYTES (2 * TILE_HALVES * 2)         // 36864 (A+B)
#define NSTAGE 3
#define GEMM_SMEM (NSTAGE * STAGE_BYTES)          // 110592
#define ROW16B (16 * STRH * 2)                    // 2304 bytes per 16 rows

__device__ __forceinline__ void gload(uint32_t sA, uint32_t sB,
                                      const __half* __restrict__ A,
                                      const __half* __restrict__ W,
                                      int m0, int n0, int kc, int tid)
{
    #pragma unroll
    for (int i = 0; i < 8; i++) {
        const int id = tid + i * 128;             // 0..1023
        const int r  = id >> 3;                   // 0..127
        const int c8 = (id & 7) * 8;              // halves
        cp_async16(sA + (r * STRH + c8) * 2, A + (size_t)(m0 + r) * E_ + kc + c8);
        cp_async16(sB + (r * STRH + c8) * 2, W + (size_t)(n0 + r) * E_ + kc + c8);
    }
}

template<int OUT>
__device__ __forceinline__ void gemm_core(const __half* __restrict__ A,
                                          const __half* __restrict__ W,
                                          const float* __restrict__ bias,
                                          void* __restrict__ Cout)
{
    extern __shared__ __align__(16) char smc[];
    const uint32_t sbase = smem_u32(smc);

    const int tid  = threadIdx.x;
    const int wid  = tid >> 5;
    const int lane = tid & 31;
    const int g    = lane >> 2;
    const int t    = lane & 3;
    const int wm   = (wid >> 1) * 64;
    const int wn   = (wid & 1) * 64;
    const int m0   = blockIdx.y * GBM;
    const int n0   = blockIdx.x * GBN;

    // ldmatrix per-thread base offsets (bytes within a stage)
    // A x4: mats (rows 0-7,klo)(rows 8-15,klo)(rows 0-7,khi)(rows 8-15,khi)
    const uint32_t aoff = ((wm + (lane & 15)) * STRH + 8 * (lane >> 4)) * 2;
    // B x4: mats (n 0-7,klo)(n 0-7,khi)(n 8-15,klo)(n 8-15,khi)
    const uint32_t boff = (uint32_t)(TILE_HALVES * 2) +
        ((wn + (lane & 7) + 8 * (lane >> 4)) * STRH + 8 * ((lane >> 3) & 1)) * 2;

    float acc[4][8][4] = {};
    const int KTILES = E_ / GBK;   // 16

    gload(sbase, sbase + TILE_HALVES * 2, A, W, m0, n0, 0, tid);
    CP_COMMIT();
    gload(sbase + STAGE_BYTES, sbase + STAGE_BYTES + TILE_HALVES * 2,
          A, W, m0, n0, GBK, tid);
    CP_COMMIT();

    int s = 0;
    for (int kt = 0; kt < KTILES; kt++) {
        if (kt == KTILES - 1) { CP_WAIT(0); } else { CP_WAIT(1); }
        __syncthreads();

        if (kt + 2 < KTILES) {
            int ps = s + 2; if (ps >= NSTAGE) ps -= NSTAGE;
            const uint32_t pb = sbase + ps * STAGE_BYTES;
            gload(pb, pb + TILE_HALVES * 2, A, W, m0, n0, (kt + 2) * GBK, tid);
            CP_COMMIT();
        }

        const uint32_t sb = sbase + s * STAGE_BYTES;

        uint32_t bf[2][4][4];
        #pragma unroll
        for (int i = 0; i < 4; i++) ldsm4(bf[0][i], sb + boff + i * ROW16B);

        #pragma unroll
        for (int kk = 0; kk < 4; kk++) {
            uint32_t af[4][4];
            #pragma unroll
            for (int mi = 0; mi < 4; mi++)
                ldsm4(af[mi], sb + aoff + mi * ROW16B + kk * 32);
            if (kk < 3) {
                #pragma unroll
                for (int i = 0; i < 4; i++)
                    ldsm4(bf[(kk + 1) & 1][i], sb + boff + i * ROW16B + (kk + 1) * 32);
            }
            const uint32_t (*bc)[4] = bf[kk & 1];
            #pragma unroll
            for (int mi = 0; mi < 4; mi++) {
                #pragma unroll
                for (int i = 0; i < 4; i++) {
                    mma_f16(acc[mi][2 * i],     af[mi], &bc[i][0]);
                    mma_f16(acc[mi][2 * i + 1], af[mi], &bc[i][2]);
                }
            }
        }

        s = s + 1; if (s >= NSTAGE) s = 0;
    }

    #pragma unroll
    for (int ni = 0; ni < 8; ni++) {
        const int col = n0 + wn + ni * 8 + 2 * t;
        const float2 bv = *(const float2*)(bias + col);
        #pragma unroll
        for (int mi = 0; mi < 4; mi++) {
            const int r0 = m0 + wm + mi * 16 + g;
            const float e0 = acc[mi][ni][0] + bv.x;
            const float e1 = acc[mi][ni][1] + bv.y;
            const float e2 = acc[mi][ni][2] + bv.x;
            const float e3 = acc[mi][ni][3] + bv.y;
            if (OUT == 0) {
                float* Cf = (float*)Cout;
                *(float2*)(Cf + (size_t)r0 * E_ + col)       = make_float2(e0, e1);
                *(float2*)(Cf + (size_t)(r0 + 8) * E_ + col) = make_float2(e2, e3);
            } else if (OUT == 1) {
                __half* Ch = (__half*)Cout;
                *(__half2*)(Ch + (size_t)r0 * E_ + col)       = __floats2half2_rn(e0, e1);
                *(__half2*)(Ch + (size_t)(r0 + 8) * E_ + col) = __floats2half2_rn(e2, e3);
            } else {
                // V^T scatter: Vt[((b*H + h)*DK + dk)*T + seq]
                __half* Vt = (__half*)Cout;
                const int bb  = r0 >> 10;
                const int seq = r0 & 1023;
                const size_t base = ((size_t)(bb * H_ + (col >> 6)) * DK_ + (col & 63)) * T_ + seq;
                Vt[base]          = __float2half_rn(e0);
                Vt[base + T_]     = __float2half_rn(e1);
                Vt[base + 8]      = __float2half_rn(e2);
                Vt[base + T_ + 8] = __float2half_rn(e3);
            }
        }
    }
}

__global__ void __launch_bounds__(128)
gemm_qkv(const __half* __restrict__ q, const __half* __restrict__ k, const __half* __restrict__ v,
         const __half* __restrict__ Wh,
         const float* __restrict__ bq, const float* __restrict__ bk, const float* __restrict__ bv,
         __half* __restrict__ Cq, __half* __restrict__ Ck, __half* __restrict__ CvT)
{
    const int z = blockIdx.z;
    if (z == 0)      gemm_core<1>(q, Wh,                 bq, Cq);
    else if (z == 1) gemm_core<1>(k, Wh + 1 * E_ * E_,   bk, Ck);
    else             gemm_core<2>(v, Wh + 2 * E_ * E_,   bv, CvT);
}

__global__ void __launch_bounds__(128)
gemm_o(const __half* __restrict__ A, const __half* __restrict__ W,
       const float* __restrict__ bias, float* __restrict__ C)
{
    gemm_core<0>(A, W, bias, C);
}

// ---------------------------------------------------------------------------
// fp16 tensor-core flash attention (unchanged from R13).
// ---------------------------------------------------------------------------
#define ASTH 72
#define KHALF (64 * ASTH)                          // 4608 halves/stage tile
#define KOFF(s) ((s) * KHALF)
#define VOFF(s) (2 * KHALF + (s) * KHALF)
#define QOFF    (4 * KHALF)                        // 18432
#define WSB     ((QOFF + 128 * ASTH) * 2)          // 55296
#define ATTN_SMEM (WSB + 2 * 128 * 4)              // 56320

__global__ void __launch_bounds__(256)
attn_tc(const __half* __restrict__ Qh, const __half* __restrict__ Kh,
        const __half* __restrict__ Vt, const float* __restrict__ w,
        __half* __restrict__ Oh)
{
    extern __shared__ __align__(16) char smc[];
    __half* smh = (__half*)smc;
    float* wsf  = (float*)(smc + WSB);
    const uint32_t sbase = smem_u32(smc);
    const int b   = blockIdx.z;
    const int h   = blockIdx.y;
    const int q0  = blockIdx.x * 128;
    const int tid = threadIdx.x;
    const int wid = tid >> 5;
    const int lane = tid & 31;
    const int g = lane >> 2;
    const int t = lane & 3;
    const int wq = wid * 16;

    {
        const __half* Qg = Qh + (size_t)(b * T_ + q0) * E_ + h * DK_;
        #pragma unroll
        for (int i = 0; i < 4; i++) {
            const int id = tid + i * 256;
            const int r  = id >> 3;
            const int c8 = (id & 7) * 8;
            cp_async16(sbase + (QOFF + r * ASTH + c8) * 2, Qg + (size_t)r * E_ + c8);
        }
        CP_COMMIT();
    }
    {
        const __half* Kg = Kh + (size_t)(b * T_) * E_ + h * DK_;
        const __half* Vg = Vt + (size_t)((b * H_ + h) * DK_) * T_;
        #pragma unroll
        for (int i = 0; i < 2; i++) {
            const int id = tid + i * 256;
            const int r  = id >> 3;
            const int c8 = (id & 7) * 8;
            cp_async16(sbase + (KOFF(0) + r * ASTH + c8) * 2, Kg + (size_t)r * E_ + c8);
            cp_async16(sbase + (VOFF(0) + r * ASTH + c8) * 2, Vg + (size_t)r * T_ + c8);
        }
        CP_COMMIT();
    }
    if (tid < 64) {
        const float wv = w[b * T_ + tid];
        wsf[tid * 2 + 0] = wv * wv * 0.125f * 1.44269504f;
        wsf[tid * 2 + 1] = (wv < 1e-5f) ? -INFINITY : 0.0f;
    }

    CP_WAIT(1);
    __syncthreads();

    const uint32_t* Qw = (const uint32_t*)(smh + QOFF);
    uint32_t aq[4][4];
    #pragma unroll
    for (int ks = 0; ks < 4; ks++) {
        const int kw = ks * 8 + t;
        aq[ks][0] = Qw[(wq + g) * 36 + kw];
        aq[ks][1] = Qw[(wq + g + 8) * 36 + kw];
        aq[ks][2] = Qw[(wq + g) * 36 + kw + 4];
        aq[ks][3] = Qw[(wq + g + 8) * 36 + kw + 4];
    }

    float acc[8][4] = {};
    float m0 = -INFINITY, m1 = -INFINITY, l0 = 0.f, l1 = 0.f;

    const int NT = T_ / 64;   // 16
    for (int kt = 0; kt < NT; kt++) {
        const int s = kt & 1;

        CP_WAIT(0);
        __syncthreads();

        if (kt + 1 < NT) {
            const int ns = 1 - s;
            const __half* Kg = Kh + (size_t)(b * T_ + (kt + 1) * 64) * E_ + h * DK_;
            const __half* Vg = Vt + (size_t)((b * H_ + h) * DK_) * T_ + (kt + 1) * 64;
            #pragma unroll
            for (int i = 0; i < 2; i++) {
                const int id = tid + i * 256;
                const int r  = id >> 3;
                const int c8 = (id & 7) * 8;
                cp_async16(sbase + (KOFF(ns) + r * ASTH + c8) * 2, Kg + (size_t)r * E_ + c8);
                cp_async16(sbase + (VOFF(ns) + r * ASTH + c8) * 2, Vg + (size_t)r * T_ + c8);
            }
            CP_COMMIT();
            if (tid < 64) {
                const float wv = w[b * T_ + (kt + 1) * 64 + tid];
                wsf[ns * 128 + tid * 2 + 0] = wv * wv * 0.125f * 1.44269504f;
                wsf[ns * 128 + tid * 2 + 1] = (wv < 1e-5f) ? -INFINITY : 0.0f;
            }
        }

        const uint32_t* Kw = (const uint32_t*)(smh + KOFF(s));
        const uint32_t* Vw = (const uint32_t*)(smh + VOFF(s));
        const float* wsl = wsf + s * 128;

        float sc[8][4] = {};
        #pragma unroll
        for (int ks = 0; ks < 4; ks++) {
            const int kw = ks * 8 + t;
            #pragma unroll
            for (int nt = 0; nt < 8; nt++) {
                uint32_t bfk[2];
                bfk[0] = Kw[(nt * 8 + g) * 36 + kw];
                bfk[1] = Kw[(nt * 8 + g) * 36 + kw + 4];
                mma_f16(sc[nt], aq[ks], bfk);
            }
        }

        float tmax0 = -INFINITY, tmax1 = -INFINITY;
        #pragma unroll
        for (int nt = 0; nt < 8; nt++) {
            const float4 wm4 = *(const float4*)&wsl[(nt * 8 + 2 * t) * 2];
            sc[nt][0] = sc[nt][0] * wm4.x + wm4.y;
            sc[nt][1] = sc[nt][1] * wm4.z + wm4.w;
            sc[nt][2] = sc[nt][2] * wm4.x + wm4.y;
            sc[nt][3] = sc[nt][3] * wm4.z + wm4.w;
            tmax0 = fmaxf(tmax0, fmaxf(sc[nt][0], sc[nt][1]));
            tmax1 = fmaxf(tmax1, fmaxf(sc[nt][2], sc[nt][3]));
        }
        tmax0 = fmaxf(tmax0, __shfl_xor_sync(0xffffffffu, tmax0, 1));
        tmax0 = fmaxf(tmax0, __shfl_xor_sync(0xffffffffu, tmax0, 2));
        tmax1 = fmaxf(tmax1, __shfl_xor_sync(0xffffffffu, tmax1, 1));
        tmax1 = fmaxf(tmax1, __shfl_xor_sync(0xffffffffu, tmax1, 2));

        const float nm0 = fmaxf(m0, tmax0);
        const float nm1 = fmaxf(m1, tmax1);
        const float sm0 = fmaxf(nm0, -1e38f);
        const float sm1 = fmaxf(nm1, -1e38f);
        const float c0  = ex2(fmaxf(m0, -1e38f) - sm0);
        const float c1  = ex2(fmaxf(m1, -1e38f) - sm1);
        m0 = nm0; m1 = nm1;
        l0 *= c0;  l1 *= c1;
        #pragma unroll
        for (int nt = 0; nt < 8; nt++) {
            acc[nt][0] *= c0; acc[nt][1] *= c0;
            acc[nt][2] *= c1; acc[nt][3] *= c1;
        }

        #pragma unroll
        for (int nt = 0; nt < 8; nt++) {
            sc[nt][0] = ex2(sc[nt][0] - sm0);
            sc[nt][1] = ex2(sc[nt][1] - sm0);
            sc[nt][2] = ex2(sc[nt][2] - sm1);
            sc[nt][3] = ex2(sc[nt][3] - sm1);
            l0 += sc[nt][0] + sc[nt][1];
            l1 += sc[nt][2] + sc[nt][3];
        }

        #pragma unroll
        for (int ks = 0; ks < 4; ks++) {
            uint32_t ap[4];
            ap[0] = pack_h2(sc[2 * ks][0],     sc[2 * ks][1]);
            ap[1] = pack_h2(sc[2 * ks][2],     sc[2 * ks][3]);
            ap[2] = pack_h2(sc[2 * ks + 1][0], sc[2 * ks + 1][1]);
            ap[3] = pack_h2(sc[2 * ks + 1][2], sc[2 * ks + 1][3]);
            const int kw = ks * 8 + t;
            #pragma unroll
            for (int nd = 0; nd < 8; nd++) {
                uint32_t bfv[2];
                bfv[0] = Vw[(nd * 8 + g) * 36 + kw];
                bfv[1] = Vw[(nd * 8 + g) * 36 + kw + 4];
                mma_f16(acc[nd], ap, bfv);
            }
        }
    }

    l0 += __shfl_xor_sync(0xffffffffu, l0, 1);
    l0 += __shfl_xor_sync(0xffffffffu, l0, 2);
    l1 += __shfl_xor_sync(0xffffffffu, l1, 1);
    l1 += __shfl_xor_sync(0xffffffffu, l1, 2);
    const float inv0 = 1.f / l0;
    const float inv1 = 1.f / l1;

    const int row0 = b * T_ + q0 + wq + g;
    #pragma unroll
    for (int nd = 0; nd < 8; nd++) {
        const int col = h * DK_ + nd * 8 + 2 * t;
        *(__half2*)(Oh + (size_t)row0 * E_ + col) =
            __floats2half2_rn(acc[nd][0] * inv0, acc[nd][1] * inv0);
        *(__half2*)(Oh + (size_t)(row0 + 8) * E_ + col) =
            __floats2half2_rn(acc[nd][2] * inv1, acc[nd][3] * inv1);
    }
}

// ---------------------------------------------------------------------------
extern "C" void kernel_launch(void* const* d_in, const int* in_sizes, int n_in,
                              void* d_out, int out_size)
{
    const float* q  = (const float*)d_in[0];
    const float* k  = (const float*)d_in[1];
    const float* v  = (const float*)d_in[2];
    const float* w  = (const float*)d_in[3];
    const float* Wq = (const float*)d_in[4];
    const float* bq = (const float*)d_in[5];
    const float* Wk = (const float*)d_in[6];
    const float* bk = (const float*)d_in[7];
    const float* Wv = (const float*)d_in[8];
    const float* bv = (const float*)d_in[9];
    const float* Wo = (const float*)d_in[10];
    const float* bo = (const float*)d_in[11];
    float* out = (float*)d_out;

    __half *qh, *kh, *vh, *Wh, *Qh, *Kh, *Vth, *Ohp;
    cudaGetSymbolAddress((void**)&qh,  g_qh);
    cudaGetSymbolAddress((void**)&kh,  g_kh);
    cudaGetSymbolAddress((void**)&vh,  g_vh);
    cudaGetSymbolAddress((void**)&Wh,  g_Wh);
    cudaGetSymbolAddress((void**)&Qh,  g_Qh);
    cudaGetSymbolAddress((void**)&Kh,  g_Kh);
    cudaGetSymbolAddress((void**)&Vth, g_Vth);
    cudaGetSymbolAddress((void**)&Ohp, g_Oh);

    cudaFuncSetAttribute(gemm_qkv, cudaFuncAttributeMaxDynamicSharedMemorySize, GEMM_SMEM);
    cudaFuncSetAttribute(gemm_o,   cudaFuncAttributeMaxDynamicSharedMemorySize, GEMM_SMEM);
    cudaFuncSetAttribute(attn_tc,  cudaFuncAttributeMaxDynamicSharedMemorySize, ATTN_SMEM);

    // 1) convert inputs + weights to fp16
    preconv<<<16384, 256>>>((const float4*)q, (const float4*)k, (const float4*)v,
                            (const float4*)Wq, (const float4*)Wk,
                            (const float4*)Wv, (const float4*)Wo,
                            qh, kh, vh, Wh);

    // 2) QKV projections (V written transposed per head)
    const dim3 qkvGrid(E_ / GBN, M_ / GBM, 3);   // (8, 32, 3)
    gemm_qkv<<<qkvGrid, 128, GEMM_SMEM>>>(qh, kh, vh, Wh, bq, bk, bv, Qh, Kh, Vth);

    // 3) attention
    const dim3 aGrid(T_ / 128, H_, B_);          // (8, 16, 4)
    attn_tc<<<aGrid, 256, ATTN_SMEM>>>(Qh, Kh, Vth, w, Ohp);

    // 4) output projection
    const dim3 oGrid(E_ / GBN, M_ / GBM);        // (8, 32)
    gemm_o<<<oGrid, 128, GEMM_SMEM>>>(Ohp, Wh + 3 * (size_t)E_ * E_, bo, out);
}

// round 15
// speedup vs baseline: 1.9639x; 1.0394x over previous
#include <cuda_runtime.h>
#include <cuda_fp16.h>
#include <math.h>
#include <stdint.h>

#define B_   4
#define T_   1024
#define E_   1024
#define H_   16
#define DK_  64
#define M_   (B_ * T_)        // 4096 rows

// Scratch (allocation-free rule: __device__ globals) — all fp16
__device__ __half g_qh[M_ * E_];
__device__ __half g_kh[M_ * E_];
__device__ __half g_vh[M_ * E_];
__device__ __half g_Wh[4 * E_ * E_];   // Wq, Wk, Wv, Wo
__device__ __half g_Qh[M_ * E_];
__device__ __half g_Kh[M_ * E_];
__device__ __half g_Vth[M_ * E_];      // V^T per head: [b][h][dk][seq]
__device__ __half g_Oh[M_ * E_];

// ---------------------------------------------------------------------------
// helpers
// ---------------------------------------------------------------------------
__device__ __forceinline__ uint32_t smem_u32(const void* p) {
    uint32_t a;
    asm("{ .reg .u64 t; cvta.to.shared.u64 t, %1; cvt.u32.u64 %0, t; }"
        : "=r"(a) : "l"(p));
    return a;
}
__device__ __forceinline__ void cp_async16(uint32_t sdst, const void* gsrc) {
    asm volatile("cp.async.cg.shared.global [%0], [%1], 16;"
                 :: "r"(sdst), "l"(gsrc) : "memory");
}
#define CP_COMMIT() asm volatile("cp.async.commit_group;" ::: "memory")
#define CP_WAIT(n)  asm volatile("cp.async.wait_group %0;" :: "n"(n) : "memory")

__device__ __forceinline__ float ex2(float x) {
    float r; asm("ex2.approx.f32 %0, %1;" : "=f"(r) : "f"(x)); return r;
}
__device__ __forceinline__ uint32_t pack_h2(float lo, float hi) {
    __half2 h = __floats2half2_rn(lo, hi);
    return *(uint32_t*)&h;
}
__device__ __forceinline__ void mma_f16(float* c, const uint32_t* a, const uint32_t* b) {
    asm volatile(
        "mma.sync.aligned.m16n8k16.row.col.f32.f16.f16.f32 "
        "{%0,%1,%2,%3}, {%4,%5,%6,%7}, {%8,%9}, {%0,%1,%2,%3};"
        : "+f"(c[0]), "+f"(c[1]), "+f"(c[2]), "+f"(c[3])
        : "r"(a[0]), "r"(a[1]), "r"(a[2]), "r"(a[3]), "r"(b[0]), "r"(b[1]));
}
__device__ __forceinline__ void ldsm4(uint32_t* r, uint32_t addr) {
    asm volatile("ldmatrix.sync.aligned.m8n8.x4.shared.b16 {%0,%1,%2,%3}, [%4];"
        : "=r"(r[0]), "=r"(r[1]), "=r"(r[2]), "=r"(r[3]) : "r"(addr));
}

// ---------------------------------------------------------------------------
// Pre-convert kernel: fp32 -> fp16 for q,k,v and the 4 weight matrices.
// ---------------------------------------------------------------------------
#define SEG_IN  (M_ * E_ / 4)      // 1,048,576 float4 per q/k/v
#define SEG_W   (E_ * E_ / 4)
__global__ void __launch_bounds__(256)
preconv(const float4* __restrict__ q, const float4* __restrict__ k,
        const float4* __restrict__ v,
        const float4* __restrict__ Wq, const float4* __restrict__ Wk,
        const float4* __restrict__ Wv, const float4* __restrict__ Wo,
        __half* __restrict__ qh, __half* __restrict__ kh,
        __half* __restrict__ vh, __half* __restrict__ Wh)
{
    int i = blockIdx.x * 256 + threadIdx.x;       // 0 .. 4M-1
    float4 x;
    __half* dst;
    int off;
    if (i < 3 * SEG_IN) {
        const int seg = i / SEG_IN;
        off = i - seg * SEG_IN;
        x   = ((seg == 0) ? q : (seg == 1) ? k : v)[off];
        dst = (seg == 0) ? qh : (seg == 1) ? kh : vh;
    } else {
        i -= 3 * SEG_IN;
        const int seg = i / SEG_W;
        x   = ((seg == 0) ? Wq : (seg == 1) ? Wk : (seg == 2) ? Wv : Wo)[i - seg * SEG_W];
        dst = Wh;
        off = i;
    }
    uint2 u;
    u.x = pack_h2(x.x, x.y);
    u.y = pack_h2(x.z, x.w);
    *(uint2*)(dst + 4 * off) = u;
}

// ---------------------------------------------------------------------------
// fp16 mma.sync GEMM core:  C[4096,1024] = A[4096,1024] @ W[1024,1024]^T + bias
// 128x128 CTA tile, BK=64 halves, 128 threads (4 warps 2x2), warp tile 64x64.
// 3-stage cp.async pipeline; ldmatrix.x4 fragment loads; BOTH A and B
// fragments double-buffered across kk steps.
// OUT: 0 = fp32 store + bias; 1 = fp16 store + bias; 2 = fp16 V^T scatter.
// ---------------------------------------------------------------------------
#define GBM 128
#define GBN 128
#define GBK 64
#define STRH 72                                   // halves per smem row
#define TILE_HALVES (128 * STRH)                  // 9216
#define STAGE_BYTES (2 * TILE_HALVES * 2)         // 36864 (A+B)
#define NSTAGE 3
#define GEMM_SMEM (NSTAGE * STAGE_BYTES)          // 110592
#define ROW16B (16 * STRH * 2)                    // 2304 bytes per 16 rows

__device__ __forceinline__ void gload(uint32_t sA, uint32_t sB,
                                      const __half* __restrict__ A,
                                      const __half* __restrict__ W,
                                      int m0, int n0, int kc, int tid)
{
    #pragma unroll
    for (int i = 0; i < 8; i++) {
        const int id = tid + i * 128;             // 0..1023
        const int r  = id >> 3;                   // 0..127
        const int c8 = (id & 7) * 8;              // halves
        cp_async16(sA + (r * STRH + c8) * 2, A + (size_t)(m0 + r) * E_ + kc + c8);
        cp_async16(sB + (r * STRH + c8) * 2, W + (size_t)(n0 + r) * E_ + kc + c8);
    }
}

template<int OUT>
__device__ __forceinline__ void gemm_core(const __half* __restrict__ A,
                                          const __half* __restrict__ W,
                                          const float* __restrict__ bias,
                                          void* __restrict__ Cout)
{
    extern __shared__ __align__(16) char smc[];
    const uint32_t sbase = smem_u32(smc);

    const int tid  = threadIdx.x;
    const int wid  = tid >> 5;
    const int lane = tid & 31;
    const int g    = lane >> 2;
    const int t    = lane & 3;
    const int wm   = (wid >> 1) * 64;
    const int wn   = (wid & 1) * 64;
    const int m0   = blockIdx.y * GBM;
    const int n0   = blockIdx.x * GBN;

    // ldmatrix per-thread base offsets (bytes within a stage)
    const uint32_t aoff = ((wm + (lane & 15)) * STRH + 8 * (lane >> 4)) * 2;
    const uint32_t boff = (uint32_t)(TILE_HALVES * 2) +
        ((wn + (lane & 7) + 8 * (lane >> 4)) * STRH + 8 * ((lane >> 3) & 1)) * 2;

    float acc[4][8][4] = {};
    const int KTILES = E_ / GBK;   // 16

    gload(sbase, sbase + TILE_HALVES * 2, A, W, m0, n0, 0, tid);
    CP_COMMIT();
    gload(sbase + STAGE_BYTES, sbase + STAGE_BYTES + TILE_HALVES * 2,
          A, W, m0, n0, GBK, tid);
    CP_COMMIT();

    int s = 0;
    for (int kt = 0; kt < KTILES; kt++) {
        if (kt == KTILES - 1) { CP_WAIT(0); } else { CP_WAIT(1); }
        __syncthreads();

        if (kt + 2 < KTILES) {
            int ps = s + 2; if (ps >= NSTAGE) ps -= NSTAGE;
            const uint32_t pb = sbase + ps * STAGE_BYTES;
            gload(pb, pb + TILE_HALVES * 2, A, W, m0, n0, (kt + 2) * GBK, tid);
            CP_COMMIT();
        }

        const uint32_t sb = sbase + s * STAGE_BYTES;

        uint32_t af[2][4][4], bf[2][4][4];
        #pragma unroll
        for (int mi = 0; mi < 4; mi++) ldsm4(af[0][mi], sb + aoff + mi * ROW16B);
        #pragma unroll
        for (int i = 0; i < 4; i++)  ldsm4(bf[0][i], sb + boff + i * ROW16B);

        #pragma unroll
        for (int kk = 0; kk < 4; kk++) {
            const int cur = kk & 1, nxt = cur ^ 1;
            if (kk < 3) {
                #pragma unroll
                for (int mi = 0; mi < 4; mi++)
                    ldsm4(af[nxt][mi], sb + aoff + mi * ROW16B + (kk + 1) * 32);
                #pragma unroll
                for (int i = 0; i < 4; i++)
                    ldsm4(bf[nxt][i], sb + boff + i * ROW16B + (kk + 1) * 32);
            }
            #pragma unroll
            for (int mi = 0; mi < 4; mi++) {
                #pragma unroll
                for (int i = 0; i < 4; i++) {
                    mma_f16(acc[mi][2 * i],     af[cur][mi], &bf[cur][i][0]);
                    mma_f16(acc[mi][2 * i + 1], af[cur][mi], &bf[cur][i][2]);
                }
            }
        }

        s = s + 1; if (s >= NSTAGE) s = 0;
    }

    #pragma unroll
    for (int ni = 0; ni < 8; ni++) {
        const int col = n0 + wn + ni * 8 + 2 * t;
        const float2 bv = *(const float2*)(bias + col);
        #pragma unroll
        for (int mi = 0; mi < 4; mi++) {
            const int r0 = m0 + wm + mi * 16 + g;
            const float e0 = acc[mi][ni][0] + bv.x;
            const float e1 = acc[mi][ni][1] + bv.y;
            const float e2 = acc[mi][ni][2] + bv.x;
            const float e3 = acc[mi][ni][3] + bv.y;
            if (OUT == 0) {
                float* Cf = (float*)Cout;
                *(float2*)(Cf + (size_t)r0 * E_ + col)       = make_float2(e0, e1);
                *(float2*)(Cf + (size_t)(r0 + 8) * E_ + col) = make_float2(e2, e3);
            } else if (OUT == 1) {
                __half* Ch = (__half*)Cout;
                *(__half2*)(Ch + (size_t)r0 * E_ + col)       = __floats2half2_rn(e0, e1);
                *(__half2*)(Ch + (size_t)(r0 + 8) * E_ + col) = __floats2half2_rn(e2, e3);
            } else {
                // V^T scatter: Vt[((b*H + h)*DK + dk)*T + seq]
                __half* Vt = (__half*)Cout;
                const int bb  = r0 >> 10;
                const int seq = r0 & 1023;
                const size_t base = ((size_t)(bb * H_ + (col >> 6)) * DK_ + (col & 63)) * T_ + seq;
                Vt[base]          = __float2half_rn(e0);
                Vt[base + T_]     = __float2half_rn(e1);
                Vt[base + 8]      = __float2half_rn(e2);
                Vt[base + T_ + 8] = __float2half_rn(e3);
            }
        }
    }
}

__global__ void __launch_bounds__(128)
gemm_qkv(const __half* __restrict__ q, const __half* __restrict__ k, const __half* __restrict__ v,
         const __half* __restrict__ Wh,
         const float* __restrict__ bq, const float* __restrict__ bk, const float* __restrict__ bv,
         __half* __restrict__ Cq, __half* __restrict__ Ck, __half* __restrict__ CvT)
{
    const int z = blockIdx.z;
    if (z == 0)      gemm_core<1>(q, Wh,                 bq, Cq);
    else if (z == 1) gemm_core<1>(k, Wh + 1 * E_ * E_,   bk, Ck);
    else             gemm_core<2>(v, Wh + 2 * E_ * E_,   bv, CvT);
}

__global__ void __launch_bounds__(128)
gemm_o(const __half* __restrict__ A, const __half* __restrict__ W,
       const float* __restrict__ bias, float* __restrict__ C)
{
    gemm_core<0>(A, W, bias, C);
}

// ---------------------------------------------------------------------------
// fp16 tensor-core flash attention — ldmatrix fragment loads for Q/K/V.
// grid (T/128, H, B), 256 threads = 8 warps x 16 query rows.
// ---------------------------------------------------------------------------
#define ASTH 72
#define KHALF (64 * ASTH)                          // 4608 halves/stage tile
#define KOFF(s) ((s) * KHALF)
#define VOFF(s) (2 * KHALF + (s) * KHALF)
#define QOFF    (4 * KHALF)                        // 18432
#define WSB     ((QOFF + 128 * ASTH) * 2)          // 55296
#define ATTN_SMEM (WSB + 2 * 128 * 4)              // 56320
#define ROW16A (16 * ASTH * 2)                     // 2304 bytes per 16 rows

__global__ void __launch_bounds__(256)
attn_tc(const __half* __restrict__ Qh, const __half* __restrict__ Kh,
        const __half* __restrict__ Vt, const float* __restrict__ w,
        __half* __restrict__ Oh)
{
    extern __shared__ __align__(16) char smc[];
    float* wsf  = (float*)(smc + WSB);
    const uint32_t sbase = smem_u32(smc);
    const int b   = blockIdx.z;
    const int h   = blockIdx.y;
    const int q0  = blockIdx.x * 128;
    const int tid = threadIdx.x;
    const int wid = tid >> 5;
    const int lane = tid & 31;
    const int g = lane >> 2;
    const int t = lane & 3;
    const int wq = wid * 16;

    // ldmatrix per-thread offsets (bytes, relative to tile bases)
    const uint32_t aoff = ((wq + (lane & 15)) * ASTH + 8 * (lane >> 4)) * 2;
    const uint32_t boff = (((lane & 7) + 8 * (lane >> 4)) * ASTH + 8 * ((lane >> 3) & 1)) * 2;

    // stage Q (group 0)
    {
        const __half* Qg = Qh + (size_t)(b * T_ + q0) * E_ + h * DK_;
        #pragma unroll
        for (int i = 0; i < 4; i++) {
            const int id = tid + i * 256;          // 0..1023
            const int r  = id >> 3;
            const int c8 = (id & 7) * 8;
            cp_async16(sbase + (QOFF + r * ASTH + c8) * 2, Qg + (size_t)r * E_ + c8);
        }
        CP_COMMIT();
    }
    // stage K/V tile 0 (group 1)
    {
        const __half* Kg = Kh + (size_t)(b * T_) * E_ + h * DK_;
        const __half* Vg = Vt + (size_t)((b * H_ + h) * DK_) * T_;
        #pragma unroll
        for (int i = 0; i < 2; i++) {
            const int id = tid + i * 256;          // 0..511
            const int r  = id >> 3;                // 0..63
            const int c8 = (id & 7) * 8;
            cp_async16(sbase + (KOFF(0) + r * ASTH + c8) * 2, Kg + (size_t)r * E_ + c8);
            cp_async16(sbase + (VOFF(0) + r * ASTH + c8) * 2, Vg + (size_t)r * T_ + c8);
        }
        CP_COMMIT();
    }
    if (tid < 64) {
        const float wv = w[b * T_ + tid];
        wsf[tid * 2 + 0] = wv * wv * 0.125f * 1.44269504f;
        wsf[tid * 2 + 1] = (wv < 1e-5f) ? -INFINITY : 0.0f;
    }

    CP_WAIT(1);
    __syncthreads();

    // Q fragments via ldmatrix: aq[ks][4] for 4 k-blocks of 16 dk
    uint32_t aq[4][4];
    #pragma unroll
    for (int ks = 0; ks < 4; ks++)
        ldsm4(aq[ks], sbase + QOFF * 2 + aoff + ks * 32);

    float acc[8][4] = {};
    float m0 = -INFINITY, m1 = -INFINITY, l0 = 0.f, l1 = 0.f;

    const int NT = T_ / 64;   // 16
    for (int kt = 0; kt < NT; kt++) {
        const int s = kt & 1;

        CP_WAIT(0);
        __syncthreads();

        if (kt + 1 < NT) {
            const int ns = 1 - s;
            const __half* Kg = Kh + (size_t)(b * T_ + (kt + 1) * 64) * E_ + h * DK_;
            const __half* Vg = Vt + (size_t)((b * H_ + h) * DK_) * T_ + (kt + 1) * 64;
            #pragma unroll
            for (int i = 0; i < 2; i++) {
                const int id = tid + i * 256;
                const int r  = id >> 3;
                const int c8 = (id & 7) * 8;
                cp_async16(sbase + (KOFF(ns) + r * ASTH + c8) * 2, Kg + (size_t)r * E_ + c8);
                cp_async16(sbase + (VOFF(ns) + r * ASTH + c8) * 2, Vg + (size_t)r * T_ + c8);
            }
            CP_COMMIT();
            if (tid < 64) {
                const float wv = w[b * T_ + (kt + 1) * 64 + tid];
                wsf[ns * 128 + tid * 2 + 0] = wv * wv * 0.125f * 1.44269504f;
                wsf[ns * 128 + tid * 2 + 1] = (wv < 1e-5f) ? -INFINITY : 0.0f;
            }
        }

        const uint32_t kbase = sbase + KOFF(s) * 2;
        const uint32_t vbase = sbase + VOFF(s) * 2;
        const float* wsl = wsf + s * 128;

        // ---- S = Q K^T (16x64 per warp): 16 ldsm4 + 32 MMAs ----
        float sc[8][4] = {};
        #pragma unroll
        for (int ks = 0; ks < 4; ks++) {
            #pragma unroll
            for (int j = 0; j < 4; j++) {           // 16-key blocks
                uint32_t bk4[4];
                ldsm4(bk4, kbase + boff + j * ROW16A + ks * 32);
                mma_f16(sc[2 * j],     aq[ks], &bk4[0]);
                mma_f16(sc[2 * j + 1], aq[ks], &bk4[2]);
            }
        }

        // ---- scale + mask + row max ----
        float tmax0 = -INFINITY, tmax1 = -INFINITY;
        #pragma unroll
        for (int nt = 0; nt < 8; nt++) {
            const float4 wm4 = *(const float4*)&wsl[(nt * 8 + 2 * t) * 2];
            sc[nt][0] = sc[nt][0] * wm4.x + wm4.y;
            sc[nt][1] = sc[nt][1] * wm4.z + wm4.w;
            sc[nt][2] = sc[nt][2] * wm4.x + wm4.y;
            sc[nt][3] = sc[nt][3] * wm4.z + wm4.w;
            tmax0 = fmaxf(tmax0, fmaxf(sc[nt][0], sc[nt][1]));
            tmax1 = fmaxf(tmax1, fmaxf(sc[nt][2], sc[nt][3]));
        }
        tmax0 = fmaxf(tmax0, __shfl_xor_sync(0xffffffffu, tmax0, 1));
        tmax0 = fmaxf(tmax0, __shfl_xor_sync(0xffffffffu, tmax0, 2));
        tmax1 = fmaxf(tmax1, __shfl_xor_sync(0xffffffffu, tmax1, 1));
        tmax1 = fmaxf(tmax1, __shfl_xor_sync(0xffffffffu, tmax1, 2));

        const float nm0 = fmaxf(m0, tmax0);
        const float nm1 = fmaxf(m1, tmax1);
        const float sm0 = fmaxf(nm0, -1e38f);
        const float sm1 = fmaxf(nm1, -1e38f);
        const float c0  = ex2(fmaxf(m0, -1e38f) - sm0);
        const float c1  = ex2(fmaxf(m1, -1e38f) - sm1);
        m0 = nm0; m1 = nm1;
        l0 *= c0;  l1 *= c1;
        #pragma unroll
        for (int nt = 0; nt < 8; nt++) {
            acc[nt][0] *= c0; acc[nt][1] *= c0;
            acc[nt][2] *= c1; acc[nt][3] *= c1;
        }

        // ---- p = exp2(s - m) ----
        #pragma unroll
        for (int nt = 0; nt < 8; nt++) {
            sc[nt][0] = ex2(sc[nt][0] - sm0);
            sc[nt][1] = ex2(sc[nt][1] - sm0);
            sc[nt][2] = ex2(sc[nt][2] - sm1);
            sc[nt][3] = ex2(sc[nt][3] - sm1);
            l0 += sc[nt][0] + sc[nt][1];
            l1 += sc[nt][2] + sc[nt][3];
        }

        // ---- O += P V : 16 ldsm4 + 32 MMAs (P packs straight to A-frags) ----
        #pragma unroll
        for (int ks = 0; ks < 4; ks++) {              // key blocks of 16
            uint32_t ap[4];
            ap[0] = pack_h2(sc[2 * ks][0],     sc[2 * ks][1]);
            ap[1] = pack_h2(sc[2 * ks][2],     sc[2 * ks][3]);
            ap[2] = pack_h2(sc[2 * ks + 1][0], sc[2 * ks + 1][1]);
            ap[3] = pack_h2(sc[2 * ks + 1][2], sc[2 * ks + 1][3]);
            #pragma unroll
            for (int j = 0; j < 4; j++) {             // 16-dk blocks
                uint32_t bv4[4];
                ldsm4(bv4, vbase + boff + j * ROW16A + ks * 32);
                mma_f16(acc[2 * j],     ap, &bv4[0]);
                mma_f16(acc[2 * j + 1], ap, &bv4[2]);
            }
        }
    }

    // ---- finalize ----
    l0 += __shfl_xor_sync(0xffffffffu, l0, 1);
    l0 += __shfl_xor_sync(0xffffffffu, l0, 2);
    l1 += __shfl_xor_sync(0xffffffffu, l1, 1);
    l1 += __shfl_xor_sync(0xffffffffu, l1, 2);
    const float inv0 = 1.f / l0;
    const float inv1 = 1.f / l1;

    const int row0 = b * T_ + q0 + wq + g;
    #pragma unroll
    for (int nd = 0; nd < 8; nd++) {
        const int col = h * DK_ + nd * 8 + 2 * t;
        *(__half2*)(Oh + (size_t)row0 * E_ + col) =
            __floats2half2_rn(acc[nd][0] * inv0, acc[nd][1] * inv0);
        *(__half2*)(Oh + (size_t)(row0 + 8) * E_ + col) =
            __floats2half2_rn(acc[nd][2] * inv1, acc[nd][3] * inv1);
    }
}

// ---------------------------------------------------------------------------
extern "C" void kernel_launch(void* const* d_in, const int* in_sizes, int n_in,
                              void* d_out, int out_size)
{
    const float* q  = (const float*)d_in[0];
    const float* k  = (const float*)d_in[1];
    const float* v  = (const float*)d_in[2];
    const float* w  = (const float*)d_in[3];
    const float* Wq = (const float*)d_in[4];
    const float* bq = (const float*)d_in[5];
    const float* Wk = (const float*)d_in[6];
    const float* bk = (const float*)d_in[7];
    const float* Wv = (const float*)d_in[8];
    const float* bv = (const float*)d_in[9];
    const float* Wo = (const float*)d_in[10];
    const float* bo = (const float*)d_in[11];
    float* out = (float*)d_out;

    __half *qh, *kh, *vh, *Wh, *Qh, *Kh, *Vth, *Ohp;
    cudaGetSymbolAddress((void**)&qh,  g_qh);
    cudaGetSymbolAddress((void**)&kh,  g_kh);
    cudaGetSymbolAddress((void**)&vh,  g_vh);
    cudaGetSymbolAddress((void**)&Wh,  g_Wh);
    cudaGetSymbolAddress((void**)&Qh,  g_Qh);
    cudaGetSymbolAddress((void**)&Kh,  g_Kh);
    cudaGetSymbolAddress((void**)&Vth, g_Vth);
    cudaGetSymbolAddress((void**)&Ohp, g_Oh);

    cudaFuncSetAttribute(gemm_qkv, cudaFuncAttributeMaxDynamicSharedMemorySize, GEMM_SMEM);
    cudaFuncSetAttribute(gemm_o,   cudaFuncAttributeMaxDynamicSharedMemorySize, GEMM_SMEM);
    cudaFuncSetAttribute(attn_tc,  cudaFuncAttributeMaxDynamicSharedMemorySize, ATTN_SMEM);

    // 1) convert inputs + weights to fp16
    preconv<<<16384, 256>>>((const float4*)q, (const float4*)k, (const float4*)v,
                            (const float4*)Wq, (const float4*)Wk,
                            (const float4*)Wv, (const float4*)Wo,
                            qh, kh, vh, Wh);

    // 2) QKV projections (V written transposed per head)
    const dim3 qkvGrid(E_ / GBN, M_ / GBM, 3);   // (8, 32, 3)
    gemm_qkv<<<qkvGrid, 128, GEMM_SMEM>>>(qh, kh, vh, Wh, bq, bk, bv, Qh, Kh, Vth);

    // 3) attention
    const dim3 aGrid(T_ / 128, H_, B_);          // (8, 16, 4)
    attn_tc<<<aGrid, 256, ATTN_SMEM>>>(Qh, Kh, Vth, w, Ohp);

    // 4) output projection
    const dim3 oGrid(E_ / GBN, M_ / GBM);        // (8, 32)
    gemm_o<<<oGrid, 128, GEMM_SMEM>>>(Ohp, Wh + 3 * (size_t)E_ * E_, bo, out);
}